// round 8
// baseline (speedup 1.0000x reference)
#include <cuda_runtime.h>

// Problem constants (fixed by the reference setup)
#define NN 262144
#define EE 4194304
#define HID 32
#define LYR 4
#define FULLM 0xffffffffu

// ---------------- device scratch (static, no allocation) ----------------
__device__ int   g_deg[NN];
__device__ int   g_offs[NN];
__device__ int   g_cursor[NN];
__device__ int   g_blocksum[256];
__device__ int   g_csr[EE];
__device__ __align__(16) float g_h0[NN * 16];   // layer-0 input, padded 9 -> 16
__device__ __align__(16) float g_hA[NN * 32];
__device__ __align__(16) float g_hB[NN * 32];
__device__ __align__(16) float g_agg[NN * 32];  // aggregation output
__device__ __align__(16) float g_z[NN * 32];
__device__ __align__(16) float g_acc[NN * 8];
__device__ float g_stats[LYR * 64];

// ---------------- init ----------------
__global__ void k_init(const float* __restrict__ x, const float* __restrict__ t) {
    int idx = blockIdx.x * blockDim.x + threadIdx.x;
    if (idx < NN * 16) {
        int i = idx >> 4, c = idx & 15;
        float v = 0.f;
        if (c < 8)       v = x[i * 8 + c];
        else if (c == 8) v = t[0];
        g_h0[idx] = v;
    }
    if (idx < NN) g_deg[idx] = 0;
    if (idx < LYR * 64) g_stats[idx] = 0.f;
}

// ---------------- CSR build ----------------
__global__ void k_hist(const int* __restrict__ ei) {
    int e4 = blockIdx.x * blockDim.x + threadIdx.x;
    if (e4 < EE / 4) {
        int4 d = __ldg(&((const int4*)(ei + EE))[e4]);
        atomicAdd(&g_deg[d.x], 1);
        atomicAdd(&g_deg[d.y], 1);
        atomicAdd(&g_deg[d.z], 1);
        atomicAdd(&g_deg[d.w], 1);
    }
}

__global__ void k_scan1() {
    int tid = threadIdx.x, lane = tid & 31, wid = tid >> 5;
    int g = blockIdx.x * 1024 + tid;
    int v = g_deg[g];
    int xv = v;
#pragma unroll
    for (int off = 1; off < 32; off <<= 1) {
        int y = __shfl_up_sync(FULLM, xv, off);
        if (lane >= off) xv += y;
    }
    __shared__ int wt[32];
    if (lane == 31) wt[wid] = xv;
    __syncthreads();
    if (wid == 0) {
        int w = wt[lane];
        int xi = w;
#pragma unroll
        for (int off = 1; off < 32; off <<= 1) {
            int y = __shfl_up_sync(FULLM, xi, off);
            if (lane >= off) xi += y;
        }
        wt[lane] = xi - w;
        if (lane == 31) g_blocksum[blockIdx.x] = xi;
    }
    __syncthreads();
    g_offs[g] = (xv - v) + wt[wid];
}

__global__ void k_scan2() {
    int tid = threadIdx.x, lane = tid & 31, wid = tid >> 5;
    int v = g_blocksum[tid];
    int xv = v;
#pragma unroll
    for (int off = 1; off < 32; off <<= 1) {
        int y = __shfl_up_sync(FULLM, xv, off);
        if (lane >= off) xv += y;
    }
    __shared__ int wt[8];
    if (lane == 31) wt[wid] = xv;
    __syncthreads();
    if (tid == 0) {
        int s = 0;
        for (int i = 0; i < 8; i++) { int t0 = wt[i]; wt[i] = s; s += t0; }
    }
    __syncthreads();
    int out = (xv - v) + wt[wid];
    __syncthreads();
    g_blocksum[tid] = out;
}

__global__ void k_scan3() {
    int g = blockIdx.x * blockDim.x + threadIdx.x;
    if (g < NN) {
        int o = g_offs[g] + g_blocksum[g >> 10];
        g_offs[g] = o;
        g_cursor[g] = o;
    }
}

__global__ void k_fill(const int* __restrict__ ei) {
    int e4 = blockIdx.x * blockDim.x + threadIdx.x;
    if (e4 < EE / 4) {
        int4 s = __ldg(&((const int4*)ei)[e4]);
        int4 d = __ldg(&((const int4*)(ei + EE))[e4]);
        g_csr[atomicAdd(&g_cursor[d.x], 1)] = s.x;
        g_csr[atomicAdd(&g_cursor[d.y], 1)] = s.y;
        g_csr[atomicAdd(&g_cursor[d.z], 1)] = s.z;
        g_csr[atomicAdd(&g_cursor[d.w], 1)] = s.w;
    }
}

// ---------------- aggregation: agg[i] = (1+eps)*h[i] + sum_{j->i} h[j] -----
// Warp per 32-node tile: CSR bounds preloaded into registers (1 coalesced
// load), gather quad-buffered (4 LDG.128 in flight per warp).
template <int STRIDE>
__global__ __launch_bounds__(256) void k_agg(
    const float* __restrict__ h_in, float* __restrict__ agg_out,
    const float* __restrict__ eps_p, int layer)
{
    constexpr int ROWF4 = STRIDE / 4;     // float4 lanes per row (4 or 8)
    constexpr int G     = 32 / ROWF4;     // edges per warp LDG (8 or 4)
    constexpr int NT    = NN / 32;        // node tiles
    float epsv = 1.0f + eps_p[layer];

    int tid = threadIdx.x;
    int lane = tid & 31, wid = tid >> 5;
    int grp  = lane / ROWF4;
    int r    = lane & (ROWF4 - 1);
    int wglob = blockIdx.x * (blockDim.x >> 5) + wid;
    int nwarp = gridDim.x * (blockDim.x >> 5);

    const float4* hin4 = (const float4*)h_in;
    float4* agg4 = (float4*)agg_out;

    for (int tile = wglob; tile < NT; tile += nwarp) {
        int base = tile * 32;
        int obnd  = g_offs[base + lane];                      // coalesced bounds
        int oLast = (base + 32 < NN) ? g_offs[base + 32] : EE;

        for (int n = 0; n < 32; n++) {
            int i = base + n;
            int start = __shfl_sync(FULLM, obnd, n);
            int end   = (n < 31) ? __shfl_sync(FULLM, obnd, n + 1) : oLast;

            float4 a0, a1, a2, a3;
            a1 = a2 = a3 = make_float4(0.f, 0.f, 0.f, 0.f);
            if (grp == 0) {
                float4 s4 = __ldg(&hin4[i * ROWF4 + r]);
                a0 = make_float4(epsv * s4.x, epsv * s4.y, epsv * s4.z, epsv * s4.w);
            } else {
                a0 = make_float4(0.f, 0.f, 0.f, 0.f);
            }

            for (int j0 = start; j0 < end; j0 += 32) {
                int myj = j0 + lane;
                int idx = (myj < end) ? g_csr[myj] : 0;
                int cnt = min(32, end - j0);
                int k = 0;
                for (; k + 4 * G <= cnt; k += 4 * G) {
                    int s0 = __shfl_sync(FULLM, idx, k + grp);
                    int s1 = __shfl_sync(FULLM, idx, k + G + grp);
                    int s2 = __shfl_sync(FULLM, idx, k + 2 * G + grp);
                    int s3 = __shfl_sync(FULLM, idx, k + 3 * G + grp);
                    float4 v0 = __ldg(&hin4[s0 * ROWF4 + r]);
                    float4 v1 = __ldg(&hin4[s1 * ROWF4 + r]);
                    float4 v2 = __ldg(&hin4[s2 * ROWF4 + r]);
                    float4 v3 = __ldg(&hin4[s3 * ROWF4 + r]);
                    a0.x += v0.x; a0.y += v0.y; a0.z += v0.z; a0.w += v0.w;
                    a1.x += v1.x; a1.y += v1.y; a1.z += v1.z; a1.w += v1.w;
                    a2.x += v2.x; a2.y += v2.y; a2.z += v2.z; a2.w += v2.w;
                    a3.x += v3.x; a3.y += v3.y; a3.z += v3.z; a3.w += v3.w;
                }
                for (; k + 2 * G <= cnt; k += 2 * G) {
                    int s0 = __shfl_sync(FULLM, idx, k + grp);
                    int s1 = __shfl_sync(FULLM, idx, k + G + grp);
                    float4 v0 = __ldg(&hin4[s0 * ROWF4 + r]);
                    float4 v1 = __ldg(&hin4[s1 * ROWF4 + r]);
                    a0.x += v0.x; a0.y += v0.y; a0.z += v0.z; a0.w += v0.w;
                    a1.x += v1.x; a1.y += v1.y; a1.z += v1.z; a1.w += v1.w;
                }
                for (; k < cnt; k += G) {
                    int e = k + grp;
                    int s = __shfl_sync(FULLM, idx, e & 31);
                    if (e < cnt) {
                        float4 v = __ldg(&hin4[s * ROWF4 + r]);
                        a0.x += v.x; a0.y += v.y; a0.z += v.z; a0.w += v.w;
                    }
                }
            }
            a0.x += a1.x + a2.x + a3.x;
            a0.y += a1.y + a2.y + a3.y;
            a0.z += a1.z + a2.z + a3.z;
            a0.w += a1.w + a2.w + a3.w;

#pragma unroll
            for (int off = ROWF4; off < 32; off <<= 1) {
                a0.x += __shfl_xor_sync(FULLM, a0.x, off);
                a0.y += __shfl_xor_sync(FULLM, a0.y, off);
                a0.z += __shfl_xor_sync(FULLM, a0.z, off);
                a0.w += __shfl_xor_sync(FULLM, a0.w, off);
            }
            if (grp == 0) agg4[i * ROWF4 + r] = a0;
        }
    }
}

// ---------------- MLP + BN stats: z = relu(agg@W1+b1)@W2+b2 -----------------
template <int STRIDE>
__global__ __launch_bounds__(256) void k_mlp(
    const float* __restrict__ agg, float* __restrict__ z_out,
    const float* __restrict__ W1, int w1rows, const float* __restrict__ b1,
    const float* __restrict__ W2, const float* __restrict__ b2, int layer)
{
    __shared__ float hs[8][32];
    __shared__ float rs[8][32], rq[8][32];

    int tid = threadIdx.x;
    int lane = tid & 31, wid = tid >> 5;

    float w1r[STRIDE], w2r[32];
#pragma unroll
    for (int c = 0; c < STRIDE; c++)
        w1r[c] = (c < w1rows) ? __ldg(&W1[c * 32 + lane]) : 0.f;
#pragma unroll
    for (int c = 0; c < 32; c++)
        w2r[c] = __ldg(&W2[c * 32 + lane]);
    float b1v = __ldg(&b1[lane]);
    float b2v = __ldg(&b2[lane]);

    int w  = blockIdx.x * (blockDim.x >> 5) + wid;
    int nw = gridDim.x * (blockDim.x >> 5);
    float ssum = 0.f, ssq = 0.f;

    const float4* agg4 = (const float4*)agg;

    for (int i = w; i < NN; i += nw) {
        float hid = b1v;
#pragma unroll
        for (int q = 0; q < STRIDE / 4; q++) {
            float4 a = __ldg(&agg4[i * (STRIDE / 4) + q]);
            hid = fmaf(a.x, w1r[4 * q + 0], hid);
            hid = fmaf(a.y, w1r[4 * q + 1], hid);
            hid = fmaf(a.z, w1r[4 * q + 2], hid);
            hid = fmaf(a.w, w1r[4 * q + 3], hid);
        }
        hid = fmaxf(hid, 0.f);

        hs[wid][lane] = hid;
        __syncwarp();
        float o = b2v;
        const float4* hrow = (const float4*)&hs[wid][0];
#pragma unroll
        for (int q = 0; q < 8; q++) {
            float4 hq = hrow[q];
            o = fmaf(hq.x, w2r[4 * q + 0], o);
            o = fmaf(hq.y, w2r[4 * q + 1], o);
            o = fmaf(hq.z, w2r[4 * q + 2], o);
            o = fmaf(hq.w, w2r[4 * q + 3], o);
        }
        __syncwarp();
        z_out[i * 32 + lane] = o;
        ssum += o;
        ssq  = fmaf(o, o, ssq);
    }

    rs[wid][lane] = ssum;
    rq[wid][lane] = ssq;
    __syncthreads();
    if (wid == 0) {
        float s = 0.f, q = 0.f;
#pragma unroll
        for (int ww = 0; ww < 8; ww++) { s += rs[ww][lane]; q += rq[ww][lane]; }
        atomicAdd(&g_stats[layer * 64 + lane], s);
        atomicAdd(&g_stats[layer * 64 + 32 + lane], q);
    }
}

// ---------------- BN apply + ReLU + incremental final linear ----------------
__global__ __launch_bounds__(256) void k_bn(
    const float* __restrict__ z, float* __restrict__ h_out,
    const float* __restrict__ gamma, const float* __restrict__ beta,
    const float* __restrict__ linW, const float* __restrict__ lin_b,
    int layer)
{
    __shared__ float sc[32], bi[32], lw[256];
    int tid = threadIdx.x;
    if (tid < 32) {
        float s = g_stats[layer * 64 + tid];
        float q = g_stats[layer * 64 + 32 + tid];
        float mu  = s * (1.0f / NN);
        float var = q * (1.0f / NN) - mu * mu;
        float inv = rsqrtf(var + 1e-5f);
        float g = gamma[layer * 32 + tid] * inv;
        sc[tid] = g;
        bi[tid] = beta[layer * 32 + tid] - mu * g;
    }
    for (int i = tid; i < 256; i += blockDim.x) lw[i] = linW[layer * 256 + i];
    __syncthreads();

    int lane = tid & 31, wid = tid >> 5;
    int w  = blockIdx.x * (blockDim.x >> 5) + wid;
    int nw = gridDim.x * (blockDim.x >> 5);
    for (int i = w; i < NN; i += nw) {
        float zv = z[i * 32 + lane];
        float h = fmaxf(fmaf(zv, sc[lane], bi[lane]), 0.f);
        h_out[i * 32 + lane] = h;
        float od[8];
#pragma unroll
        for (int d = 0; d < 8; d++) {
            float p = h * lw[lane * 8 + d];
#pragma unroll
            for (int off = 16; off; off >>= 1)
                p += __shfl_xor_sync(FULLM, p, off);
            od[d] = p;
        }
        if (lane < 8) {
            float v = od[lane];
            if (layer == 0) v += lin_b[lane];
            else            v += g_acc[i * 8 + lane];
            g_acc[i * 8 + lane] = v;
        }
    }
}

// ---------------- masked write-back (masks are int32) ----------------
__global__ void k_mask(const float* __restrict__ x,
                       const int* __restrict__ nm,
                       const int* __restrict__ em,
                       float* __restrict__ out)
{
    int idx = blockIdx.x * blockDim.x + threadIdx.x;
    if (idx < NN * 8) {
        int i = idx >> 3, c = idx & 7;
        bool wn = (nm[i] != 0) && (c >= 1 && c <= 5);
        bool we = (em[i] != 0) && (c >= 1 && c <= 4);
        out[idx] = (wn || we) ? g_acc[idx] : x[idx];
    }
}

// ---------------- launch ----------------
extern "C" void kernel_launch(void* const* d_in, const int* in_sizes, int n_in,
                              void* d_out, int out_size)
{
    const float* x        = (const float*)d_in[0];
    const float* t        = (const float*)d_in[1];
    const int*   ei       = (const int*)d_in[2];
    const int*   node_mask = (const int*)d_in[3];
    const int*   edge_mask = (const int*)d_in[4];
    const float* W1_first = (const float*)d_in[7];
    const float* b1_first = (const float*)d_in[8];
    const float* W2_first = (const float*)d_in[9];
    const float* b2_first = (const float*)d_in[10];
    const float* W1_rest  = (const float*)d_in[11];
    const float* b1_rest  = (const float*)d_in[12];
    const float* W2_rest  = (const float*)d_in[13];
    const float* b2_rest  = (const float*)d_in[14];
    const float* eps      = (const float*)d_in[15];
    const float* bn_gamma = (const float*)d_in[16];
    const float* bn_beta  = (const float*)d_in[17];
    const float* lin_W    = (const float*)d_in[18];
    const float* lin_b    = (const float*)d_in[19];
    float* out = (float*)d_out;

    k_init<<<(NN * 16 + 255) / 256, 256>>>(x, t);
    k_hist<<<(EE / 4 + 255) / 256, 256>>>(ei);
    k_scan1<<<256, 1024>>>();
    k_scan2<<<1, 256>>>();
    k_scan3<<<(NN + 255) / 256, 256>>>();
    k_fill<<<(EE / 4 + 255) / 256, 256>>>(ei);

    const int GB  = 148 * 8;       // for k_mlp / k_bn
    const int GBA = NN / 32 / 8;   // 1024 blocks: warp per 32-node tile

    float* h0; cudaGetSymbolAddress((void**)&h0, g_h0);
    float* ag; cudaGetSymbolAddress((void**)&ag, g_agg);
    float* zz; cudaGetSymbolAddress((void**)&zz, g_z);
    float* hA; cudaGetSymbolAddress((void**)&hA, g_hA);
    float* hB; cudaGetSymbolAddress((void**)&hB, g_hB);

    // Layer 0
    k_agg<16><<<GBA, 256>>>(h0, ag, eps, 0);
    k_mlp<16><<<GB, 256>>>(ag, zz, W1_first, 9, b1_first, W2_first, b2_first, 0);
    k_bn<<<GB, 256>>>(zz, hA, bn_gamma, bn_beta, lin_W, lin_b, 0);

    // Layer 1
    k_agg<32><<<GBA, 256>>>(hA, ag, eps, 1);
    k_mlp<32><<<GB, 256>>>(ag, zz, W1_rest + 0 * 1024, 32, b1_rest + 0 * 32,
                           W2_rest + 0 * 1024, b2_rest + 0 * 32, 1);
    k_bn<<<GB, 256>>>(zz, hB, bn_gamma, bn_beta, lin_W, lin_b, 1);

    // Layer 2
    k_agg<32><<<GBA, 256>>>(hB, ag, eps, 2);
    k_mlp<32><<<GB, 256>>>(ag, zz, W1_rest + 1 * 1024, 32, b1_rest + 1 * 32,
                           W2_rest + 1 * 1024, b2_rest + 1 * 32, 2);
    k_bn<<<GB, 256>>>(zz, hA, bn_gamma, bn_beta, lin_W, lin_b, 2);

    // Layer 3
    k_agg<32><<<GBA, 256>>>(hA, ag, eps, 3);
    k_mlp<32><<<GB, 256>>>(ag, zz, W1_rest + 2 * 1024, 32, b1_rest + 2 * 32,
                           W2_rest + 2 * 1024, b2_rest + 2 * 32, 3);
    k_bn<<<GB, 256>>>(zz, hB, bn_gamma, bn_beta, lin_W, lin_b, 3);

    k_mask<<<(NN * 8 + 255) / 256, 256>>>(x, node_mask, edge_mask, out);
}

// round 9
// speedup vs baseline: 1.1915x; 1.1915x over previous
#include <cuda_runtime.h>

// Problem constants (fixed by the reference setup)
#define NN 262144
#define EE 4194304
#define HID 32
#define LYR 4
#define FULLM 0xffffffffu

// ---------------- device scratch (static, no allocation) ----------------
__device__ int   g_deg[NN];        // zero at module load; re-zeroed by k_scan1
__device__ int   g_offs[NN];       // final exclusive prefix
__device__ int   g_cursor[NN];     // scratch: scan1 partials, then fill cursor
__device__ int   g_blocksum[256];
__device__ int   g_csr[EE];
__device__ __align__(16) float g_h0[NN * 16];   // layer-0 input, padded 9 -> 16
__device__ __align__(16) float g_hA[NN * 32];
__device__ __align__(16) float g_hB[NN * 32];
__device__ __align__(16) float g_agg[NN * 32];
__device__ __align__(16) float g_z[NN * 32];
__device__ __align__(16) float g_acc[NN * 8];
__device__ float g_stats[LYR * 64];

// ---------------- CSR build ----------------
// #0: histogram (g_deg starts zero: module init on run 1, scan1 re-zero after)
__global__ void k_hist(const int* __restrict__ ei) {
    int e = blockIdx.x * blockDim.x + threadIdx.x;
    if (e < EE) atomicAdd(&g_deg[ei[EE + e]], 1);
}

// #1: per-1024-block exclusive scan; writes partials to g_cursor, zeroes g_deg
__global__ void k_scan1() {
    int tid = threadIdx.x, lane = tid & 31, wid = tid >> 5;
    int g = blockIdx.x * 1024 + tid;
    int v = g_deg[g];
    g_deg[g] = 0;                       // dead after this read; ready for next run
    int xv = v;
#pragma unroll
    for (int off = 1; off < 32; off <<= 1) {
        int y = __shfl_up_sync(FULLM, xv, off);
        if (lane >= off) xv += y;
    }
    __shared__ int wt[32];
    if (lane == 31) wt[wid] = xv;
    __syncthreads();
    if (wid == 0) {
        int w = wt[lane];
        int xi = w;
#pragma unroll
        for (int off = 1; off < 32; off <<= 1) {
            int y = __shfl_up_sync(FULLM, xi, off);
            if (lane >= off) xi += y;
        }
        wt[lane] = xi - w;
        if (lane == 31) g_blocksum[blockIdx.x] = xi;
    }
    __syncthreads();
    g_cursor[g] = (xv - v) + wt[wid];   // block-local exclusive prefix
}

// #2: add block offsets (each block locally sums blocksums[0..bid)), finalize
__global__ void k_scan23() {
    __shared__ int bs[256];
    __shared__ int boff;
    int tid = threadIdx.x;
    if (tid < 256) bs[tid] = g_blocksum[tid];
    __syncthreads();
    if (tid == 0) {
        int s = 0;
        for (int k = 0; k < blockIdx.x; k++) s += bs[k];
        boff = s;
    }
    __syncthreads();
    int g = blockIdx.x * 1024 + tid;
    int o = g_cursor[g] + boff;
    g_offs[g] = o;
    g_cursor[g] = o;
}

// #3 (ncu-captured slot): CSR fill
__global__ void k_fill(const int* __restrict__ ei) {
    int e = blockIdx.x * blockDim.x + threadIdx.x;
    if (e < EE) {
        int d = ei[EE + e];
        int p = atomicAdd(&g_cursor[d], 1);
        g_csr[p] = ei[e];
    }
}

// #4: h0 build + stats zero
__global__ void k_init(const float* __restrict__ x, const float* __restrict__ t) {
    int idx = blockIdx.x * blockDim.x + threadIdx.x;
    if (idx < NN * 16) {
        int i = idx >> 4, c = idx & 15;
        float v = 0.f;
        if (c < 8)       v = x[i * 8 + c];
        else if (c == 8) v = t[0];
        g_h0[idx] = v;
    }
    if (idx < LYR * 64) g_stats[idx] = 0.f;
}

// ---------------- aggregation: agg[i] = (1+eps)*h[i] + sum_{j->i} h[j] -----
// Warp per node; G groups of ROWF4 lanes each fetch one float4 row-slice.
template <int STRIDE>
__global__ __launch_bounds__(256) void k_agg(
    const float* __restrict__ h_in, float* __restrict__ agg_out,
    const float* __restrict__ eps_p, int layer)
{
    constexpr int ROWF4 = STRIDE / 4;
    constexpr int G     = 32 / ROWF4;
    float epsv = 1.0f + eps_p[layer];

    int tid = threadIdx.x;
    int lane = tid & 31, wid = tid >> 5;
    int grp  = lane / ROWF4;
    int r    = lane & (ROWF4 - 1);
    int w  = blockIdx.x * (blockDim.x >> 5) + wid;
    int nw = gridDim.x * (blockDim.x >> 5);

    const float4* hin4 = (const float4*)h_in;
    float4* agg4 = (float4*)agg_out;

    for (int i = w; i < NN; i += nw) {
        float4 accA, accB;
        if (grp == 0) {
            float4 s4 = __ldg(&hin4[i * ROWF4 + r]);
            accA.x = epsv * s4.x; accA.y = epsv * s4.y;
            accA.z = epsv * s4.z; accA.w = epsv * s4.w;
        } else {
            accA.x = accA.y = accA.z = accA.w = 0.f;
        }
        accB.x = accB.y = accB.z = accB.w = 0.f;

        int start = g_offs[i];
        int end   = (i + 1 < NN) ? g_offs[i + 1] : EE;

        for (int j0 = start; j0 < end; j0 += 32) {
            int myj = j0 + lane;
            int idx = (myj < end) ? g_csr[myj] : 0;
            int cnt = min(32, end - j0);
            int k = 0;
            for (; k + 2 * G <= cnt; k += 2 * G) {
                int s0 = __shfl_sync(FULLM, idx, k + grp);
                int s1 = __shfl_sync(FULLM, idx, k + G + grp);
                float4 v0 = __ldg(&hin4[s0 * ROWF4 + r]);
                float4 v1 = __ldg(&hin4[s1 * ROWF4 + r]);
                accA.x += v0.x; accA.y += v0.y; accA.z += v0.z; accA.w += v0.w;
                accB.x += v1.x; accB.y += v1.y; accB.z += v1.z; accB.w += v1.w;
            }
            for (; k < cnt; k += G) {
                int e = k + grp;
                int s = __shfl_sync(FULLM, idx, e & 31);
                if (e < cnt) {
                    float4 v = __ldg(&hin4[s * ROWF4 + r]);
                    accA.x += v.x; accA.y += v.y; accA.z += v.z; accA.w += v.w;
                }
            }
        }
        accA.x += accB.x; accA.y += accB.y; accA.z += accB.z; accA.w += accB.w;

#pragma unroll
        for (int off = ROWF4; off < 32; off <<= 1) {
            accA.x += __shfl_xor_sync(FULLM, accA.x, off);
            accA.y += __shfl_xor_sync(FULLM, accA.y, off);
            accA.z += __shfl_xor_sync(FULLM, accA.z, off);
            accA.w += __shfl_xor_sync(FULLM, accA.w, off);
        }
        if (grp == 0) agg4[i * ROWF4 + r] = accA;
    }
}

// ---------------- MLP + BN stats: z = relu(agg@W1+b1)@W2+b2 -----------------
template <int STRIDE>
__global__ __launch_bounds__(256) void k_mlp(
    const float* __restrict__ agg, float* __restrict__ z_out,
    const float* __restrict__ W1, int w1rows, const float* __restrict__ b1,
    const float* __restrict__ W2, const float* __restrict__ b2, int layer)
{
    __shared__ float hs[8][32];
    __shared__ float rs[8][32], rq[8][32];

    int tid = threadIdx.x;
    int lane = tid & 31, wid = tid >> 5;

    float w1r[STRIDE], w2r[32];
#pragma unroll
    for (int c = 0; c < STRIDE; c++)
        w1r[c] = (c < w1rows) ? __ldg(&W1[c * 32 + lane]) : 0.f;
#pragma unroll
    for (int c = 0; c < 32; c++)
        w2r[c] = __ldg(&W2[c * 32 + lane]);
    float b1v = __ldg(&b1[lane]);
    float b2v = __ldg(&b2[lane]);

    int w  = blockIdx.x * (blockDim.x >> 5) + wid;
    int nw = gridDim.x * (blockDim.x >> 5);
    float ssum = 0.f, ssq = 0.f;

    const float4* agg4 = (const float4*)agg;

    for (int i = w; i < NN; i += nw) {
        float hid = b1v;
#pragma unroll
        for (int q = 0; q < STRIDE / 4; q++) {
            float4 a = __ldg(&agg4[i * (STRIDE / 4) + q]);
            hid = fmaf(a.x, w1r[4 * q + 0], hid);
            hid = fmaf(a.y, w1r[4 * q + 1], hid);
            hid = fmaf(a.z, w1r[4 * q + 2], hid);
            hid = fmaf(a.w, w1r[4 * q + 3], hid);
        }
        hid = fmaxf(hid, 0.f);

        hs[wid][lane] = hid;
        __syncwarp();
        float o = b2v;
        const float4* hrow = (const float4*)&hs[wid][0];
#pragma unroll
        for (int q = 0; q < 8; q++) {
            float4 hq = hrow[q];
            o = fmaf(hq.x, w2r[4 * q + 0], o);
            o = fmaf(hq.y, w2r[4 * q + 1], o);
            o = fmaf(hq.z, w2r[4 * q + 2], o);
            o = fmaf(hq.w, w2r[4 * q + 3], o);
        }
        __syncwarp();
        z_out[i * 32 + lane] = o;
        ssum += o;
        ssq  = fmaf(o, o, ssq);
    }

    rs[wid][lane] = ssum;
    rq[wid][lane] = ssq;
    __syncthreads();
    if (wid == 0) {
        float s = 0.f, q = 0.f;
#pragma unroll
        for (int ww = 0; ww < 8; ww++) { s += rs[ww][lane]; q += rq[ww][lane]; }
        atomicAdd(&g_stats[layer * 64 + lane], s);
        atomicAdd(&g_stats[layer * 64 + 32 + lane], q);
    }
}

// ---------------- BN apply + ReLU + incremental final linear ----------------
__global__ __launch_bounds__(256) void k_bn(
    const float* __restrict__ z, float* __restrict__ h_out,
    const float* __restrict__ gamma, const float* __restrict__ beta,
    const float* __restrict__ linW, const float* __restrict__ lin_b,
    int layer, int write_h)
{
    __shared__ float sc[32], bi[32], lw[256];
    int tid = threadIdx.x;
    if (tid < 32) {
        float s = g_stats[layer * 64 + tid];
        float q = g_stats[layer * 64 + 32 + tid];
        float mu  = s * (1.0f / NN);
        float var = q * (1.0f / NN) - mu * mu;
        float inv = rsqrtf(var + 1e-5f);
        float g = gamma[layer * 32 + tid] * inv;
        sc[tid] = g;
        bi[tid] = beta[layer * 32 + tid] - mu * g;
    }
    for (int i = tid; i < 256; i += blockDim.x) lw[i] = linW[layer * 256 + i];
    __syncthreads();

    int lane = tid & 31, wid = tid >> 5;
    int w  = blockIdx.x * (blockDim.x >> 5) + wid;
    int nw = gridDim.x * (blockDim.x >> 5);
    for (int i = w; i < NN; i += nw) {
        float zv = z[i * 32 + lane];
        float h = fmaxf(fmaf(zv, sc[lane], bi[lane]), 0.f);
        if (write_h) h_out[i * 32 + lane] = h;
        float od[8];
#pragma unroll
        for (int d = 0; d < 8; d++) {
            float p = h * lw[lane * 8 + d];
#pragma unroll
            for (int off = 16; off; off >>= 1)
                p += __shfl_xor_sync(FULLM, p, off);
            od[d] = p;
        }
        if (lane < 8) {
            float v = od[lane];
            if (layer == 0) v += lin_b[lane];
            else            v += g_acc[i * 8 + lane];
            g_acc[i * 8 + lane] = v;
        }
    }
}

// ---------------- masked write-back (masks are int32), float4 per node -----
__global__ void k_mask(const float* __restrict__ x,
                       const int* __restrict__ nm,
                       const int* __restrict__ em,
                       float* __restrict__ out)
{
    int i = blockIdx.x * blockDim.x + threadIdx.x;
    if (i < NN) {
        const float4* x4 = (const float4*)x;
        const float4* a4 = (const float4*)g_acc;
        float4* o4 = (float4*)out;
        float4 xlo = __ldg(&x4[i * 2 + 0]);
        float4 xhi = __ldg(&x4[i * 2 + 1]);
        float4 alo = a4[i * 2 + 0];
        float4 ahi = a4[i * 2 + 1];
        bool n = (nm[i] != 0), e = (em[i] != 0);
        bool w14 = n || e;   // cols 1..4 (node cols 1..5, edge cols 1..4)
        bool w5  = n;        // col 5
        float4 olo = xlo, ohi = xhi;
        if (w14) { olo.y = alo.y; olo.z = alo.z; olo.w = alo.w; ohi.x = ahi.x; }
        if (w5)  { ohi.y = ahi.y; }
        o4[i * 2 + 0] = olo;
        o4[i * 2 + 1] = ohi;
    }
}

// ---------------- launch ----------------
extern "C" void kernel_launch(void* const* d_in, const int* in_sizes, int n_in,
                              void* d_out, int out_size)
{
    const float* x        = (const float*)d_in[0];
    const float* t        = (const float*)d_in[1];
    const int*   ei       = (const int*)d_in[2];
    const int*   node_mask = (const int*)d_in[3];
    const int*   edge_mask = (const int*)d_in[4];
    const float* W1_first = (const float*)d_in[7];
    const float* b1_first = (const float*)d_in[8];
    const float* W2_first = (const float*)d_in[9];
    const float* b2_first = (const float*)d_in[10];
    const float* W1_rest  = (const float*)d_in[11];
    const float* b1_rest  = (const float*)d_in[12];
    const float* W2_rest  = (const float*)d_in[13];
    const float* b2_rest  = (const float*)d_in[14];
    const float* eps      = (const float*)d_in[15];
    const float* bn_gamma = (const float*)d_in[16];
    const float* bn_beta  = (const float*)d_in[17];
    const float* lin_W    = (const float*)d_in[18];
    const float* lin_b    = (const float*)d_in[19];
    float* out = (float*)d_out;

    // CSR build first so k_fill lands in the ncu capture slot (my launch #3)
    k_hist<<<(EE + 255) / 256, 256>>>(ei);      // #0
    k_scan1<<<256, 1024>>>();                   // #1 (also re-zeroes g_deg)
    k_scan23<<<256, 1024>>>();                  // #2
    k_fill<<<(EE + 255) / 256, 256>>>(ei);      // #3  <- ncu captures this
    k_init<<<(NN * 16 + 255) / 256, 256>>>(x, t); // #4

    const int GB = 148 * 8;

    float* h0; cudaGetSymbolAddress((void**)&h0, g_h0);
    float* ag; cudaGetSymbolAddress((void**)&ag, g_agg);
    float* zz; cudaGetSymbolAddress((void**)&zz, g_z);
    float* hA; cudaGetSymbolAddress((void**)&hA, g_hA);
    float* hB; cudaGetSymbolAddress((void**)&hB, g_hB);

    // Layer 0
    k_agg<16><<<GB, 256>>>(h0, ag, eps, 0);
    k_mlp<16><<<GB, 256>>>(ag, zz, W1_first, 9, b1_first, W2_first, b2_first, 0);
    k_bn<<<GB, 256>>>(zz, hA, bn_gamma, bn_beta, lin_W, lin_b, 0, 1);

    // Layer 1
    k_agg<32><<<GB, 256>>>(hA, ag, eps, 1);
    k_mlp<32><<<GB, 256>>>(ag, zz, W1_rest + 0 * 1024, 32, b1_rest + 0 * 32,
                           W2_rest + 0 * 1024, b2_rest + 0 * 32, 1);
    k_bn<<<GB, 256>>>(zz, hB, bn_gamma, bn_beta, lin_W, lin_b, 1, 1);

    // Layer 2
    k_agg<32><<<GB, 256>>>(hB, ag, eps, 2);
    k_mlp<32><<<GB, 256>>>(ag, zz, W1_rest + 1 * 1024, 32, b1_rest + 1 * 32,
                           W2_rest + 1 * 1024, b2_rest + 1 * 32, 2);
    k_bn<<<GB, 256>>>(zz, hA, bn_gamma, bn_beta, lin_W, lin_b, 2, 1);

    // Layer 3 (h never consumed afterward -> skip h store)
    k_agg<32><<<GB, 256>>>(hA, ag, eps, 3);
    k_mlp<32><<<GB, 256>>>(ag, zz, W1_rest + 2 * 1024, 32, b1_rest + 2 * 32,
                           W2_rest + 2 * 1024, b2_rest + 2 * 32, 3);
    k_bn<<<GB, 256>>>(zz, hB, bn_gamma, bn_beta, lin_W, lin_b, 3, 0);

    k_mask<<<(NN + 255) / 256, 256>>>(x, node_mask, edge_mask, out);
}

// round 10
// speedup vs baseline: 1.2091x; 1.0148x over previous
#include <cuda_runtime.h>

// Problem constants (fixed by the reference setup)
#define NN 262144
#define EE 4194304
#define HID 32
#define LYR 4
#define FULLM 0xffffffffu

// ---------------- device scratch (static, no allocation) ----------------
__device__ int   g_deg[NN];        // zeroed at module load; re-zeroed by k_scan
__device__ int   g_cursor[NN];     // block-local offsets; after fill: local ends
__device__ int   g_blocksum[256];
__device__ int   g_boff[256];      // exclusive prefix of block sums
__device__ int   g_tick;           // last-block ticket (reset each run)
__device__ int   g_csr[EE];
__device__ __align__(16) float g_agg[NN * 32];
__device__ __align__(16) float g_z[NN * 32];
__device__ __align__(16) float g_hA[NN * 32];
__device__ __align__(16) float g_hB[NN * 32];
__device__ __align__(16) float g_acc[NN * 8];
__device__ float g_stats[LYR * 64];

// ---------------- #0: degree histogram ----------------
__global__ void k_hist(const int* __restrict__ ei) {
    int e = blockIdx.x * blockDim.x + threadIdx.x;
    if (e < EE) atomicAdd(&g_deg[ei[EE + e]], 1);
}

// ---------------- #1: fused two-level scan (last-block pattern) ----------
// 256 blocks x 1024 threads. Produces: g_cursor = block-local exclusive
// prefix, g_boff = exclusive prefix of block totals. Also zeroes g_deg and
// g_stats, resets g_tick.
__global__ void k_scan() {
    __shared__ int wt[32];
    __shared__ int s_tot;
    __shared__ bool s_last;
    int tid = threadIdx.x, lane = tid & 31, wid = tid >> 5;
    int g = blockIdx.x * 1024 + tid;
    int v = g_deg[g];
    g_deg[g] = 0;                          // ready for next run
    int xv = v;
#pragma unroll
    for (int off = 1; off < 32; off <<= 1) {
        int y = __shfl_up_sync(FULLM, xv, off);
        if (lane >= off) xv += y;
    }
    if (lane == 31) wt[wid] = xv;
    __syncthreads();
    if (wid == 0) {
        int w = wt[lane];
        int xi = w;
#pragma unroll
        for (int off = 1; off < 32; off <<= 1) {
            int y = __shfl_up_sync(FULLM, xi, off);
            if (lane >= off) xi += y;
        }
        wt[lane] = xi - w;
        if (lane == 31) s_tot = xi;
    }
    __syncthreads();
    g_cursor[g] = (xv - v) + wt[wid];      // block-local exclusive prefix

    // publish block total, elect last block
    if (tid == 0) {
        g_blocksum[blockIdx.x] = s_tot;
        __threadfence();
        s_last = (atomicAdd(&g_tick, 1) == 255);
    }
    __syncthreads();
    if (s_last) {
        __shared__ int wt2[8];
        int bv = (tid < 256) ? g_blocksum[tid] : 0;
        int xi = bv;
#pragma unroll
        for (int off = 1; off < 32; off <<= 1) {
            int y = __shfl_up_sync(FULLM, xi, off);
            if (lane >= off) xi += y;
        }
        if (tid < 256 && lane == 31) wt2[wid] = xi;
        __syncthreads();
        if (tid == 0) {
            int s = 0;
            for (int k = 0; k < 8; k++) { int t0 = wt2[k]; wt2[k] = s; s += t0; }
        }
        __syncthreads();
        if (tid < 256) {
            g_boff[tid] = (xi - bv) + wt2[wid];
            g_stats[tid] = 0.f;            // LYR*64 == 256
        }
        if (tid == 0) g_tick = 0;
    }
}

// ---------------- #2: CSR fill ----------------
__global__ void k_fill(const int* __restrict__ ei) {
    int e = blockIdx.x * blockDim.x + threadIdx.x;
    if (e < EE) {
        int d = ei[EE + e];
        int p = __ldg(&g_boff[d >> 10]) + atomicAdd(&g_cursor[d], 1);
        g_csr[p] = ei[e];
    }
}

// ---------------- #3 (ncu capture slot): layer-0 aggregation --------------
// Reads x directly (32B rows, G=16 edges per warp LDG). t-column analytic:
// agg[8] = (1+eps+deg)*t. Cols 9..15 zero. agg stride = 16 floats.
__global__ __launch_bounds__(256) void k_agg0(
    const float* __restrict__ x, float* __restrict__ agg_out,
    const float* __restrict__ eps_p, const float* __restrict__ tptr)
{
    float epsv = 1.0f + eps_p[0];
    float tv = tptr[0];
    int tid = threadIdx.x, lane = tid & 31, wid = tid >> 5;
    int grp = lane >> 1, r = lane & 1;
    int w  = blockIdx.x * (blockDim.x >> 5) + wid;
    int nw = gridDim.x * (blockDim.x >> 5);
    const float4* x4 = (const float4*)x;
    float4* agg4 = (float4*)agg_out;

    for (int i = w; i < NN; i += nw) {
        int bo = __ldg(&g_boff[i >> 10]);
        int le = g_cursor[i];
        int ls = (i & 1023) ? g_cursor[i - 1] : 0;
        int start = bo + ls, end = bo + le;

        float4 accA, accB;
        accB = make_float4(0.f, 0.f, 0.f, 0.f);
        if (grp == 0) {
            float4 s4 = __ldg(&x4[i * 2 + r]);
            accA = make_float4(epsv * s4.x, epsv * s4.y, epsv * s4.z, epsv * s4.w);
        } else {
            accA = make_float4(0.f, 0.f, 0.f, 0.f);
        }

        for (int j0 = start; j0 < end; j0 += 32) {
            int myj = j0 + lane;
            int idx = (myj < end) ? g_csr[myj] : 0;
            int cnt = min(32, end - j0);
            int k = 0;
            for (; k + 32 <= cnt; k += 32) {
                int s0 = __shfl_sync(FULLM, idx, k + grp);
                int s1 = __shfl_sync(FULLM, idx, k + 16 + grp);
                float4 v0 = __ldg(&x4[s0 * 2 + r]);
                float4 v1 = __ldg(&x4[s1 * 2 + r]);
                accA.x += v0.x; accA.y += v0.y; accA.z += v0.z; accA.w += v0.w;
                accB.x += v1.x; accB.y += v1.y; accB.z += v1.z; accB.w += v1.w;
            }
            for (; k < cnt; k += 16) {
                int e2 = k + grp;
                int s = __shfl_sync(FULLM, idx, e2 & 31);
                if (e2 < cnt) {
                    float4 v = __ldg(&x4[s * 2 + r]);
                    accA.x += v.x; accA.y += v.y; accA.z += v.z; accA.w += v.w;
                }
            }
        }
        accA.x += accB.x; accA.y += accB.y; accA.z += accB.z; accA.w += accB.w;
#pragma unroll
        for (int off = 2; off < 32; off <<= 1) {
            accA.x += __shfl_xor_sync(FULLM, accA.x, off);
            accA.y += __shfl_xor_sync(FULLM, accA.y, off);
            accA.z += __shfl_xor_sync(FULLM, accA.z, off);
            accA.w += __shfl_xor_sync(FULLM, accA.w, off);
        }
        float tt = (epsv + (float)(end - start)) * tv;
        if (grp == 0) {
            agg4[i * 4 + r] = accA;
        } else if (grp == 1) {
            agg4[i * 4 + 2 + r] = (r == 0) ? make_float4(tt, 0.f, 0.f, 0.f)
                                           : make_float4(0.f, 0.f, 0.f, 0.f);
        }
    }
}

// ---------------- aggregation for layers 1..3 (32-float rows) -------------
__global__ __launch_bounds__(256) void k_agg(
    const float* __restrict__ h_in, float* __restrict__ agg_out,
    const float* __restrict__ eps_p, int layer)
{
    constexpr int ROWF4 = 8;
    constexpr int G     = 4;
    float epsv = 1.0f + eps_p[layer];

    int tid = threadIdx.x, lane = tid & 31, wid = tid >> 5;
    int grp  = lane / ROWF4;
    int r    = lane & (ROWF4 - 1);
    int w  = blockIdx.x * (blockDim.x >> 5) + wid;
    int nw = gridDim.x * (blockDim.x >> 5);

    const float4* hin4 = (const float4*)h_in;
    float4* agg4 = (float4*)agg_out;

    for (int i = w; i < NN; i += nw) {
        int bo = __ldg(&g_boff[i >> 10]);
        int le = g_cursor[i];
        int ls = (i & 1023) ? g_cursor[i - 1] : 0;
        int start = bo + ls, end = bo + le;

        float4 accA, accB;
        accB = make_float4(0.f, 0.f, 0.f, 0.f);
        if (grp == 0) {
            float4 s4 = __ldg(&hin4[i * ROWF4 + r]);
            accA = make_float4(epsv * s4.x, epsv * s4.y, epsv * s4.z, epsv * s4.w);
        } else {
            accA = make_float4(0.f, 0.f, 0.f, 0.f);
        }

        for (int j0 = start; j0 < end; j0 += 32) {
            int myj = j0 + lane;
            int idx = (myj < end) ? g_csr[myj] : 0;
            int cnt = min(32, end - j0);
            int k = 0;
            for (; k + 2 * G <= cnt; k += 2 * G) {
                int s0 = __shfl_sync(FULLM, idx, k + grp);
                int s1 = __shfl_sync(FULLM, idx, k + G + grp);
                float4 v0 = __ldg(&hin4[s0 * ROWF4 + r]);
                float4 v1 = __ldg(&hin4[s1 * ROWF4 + r]);
                accA.x += v0.x; accA.y += v0.y; accA.z += v0.z; accA.w += v0.w;
                accB.x += v1.x; accB.y += v1.y; accB.z += v1.z; accB.w += v1.w;
            }
            for (; k < cnt; k += G) {
                int e2 = k + grp;
                int s = __shfl_sync(FULLM, idx, e2 & 31);
                if (e2 < cnt) {
                    float4 v = __ldg(&hin4[s * ROWF4 + r]);
                    accA.x += v.x; accA.y += v.y; accA.z += v.z; accA.w += v.w;
                }
            }
        }
        accA.x += accB.x; accA.y += accB.y; accA.z += accB.z; accA.w += accB.w;
#pragma unroll
        for (int off = ROWF4; off < 32; off <<= 1) {
            accA.x += __shfl_xor_sync(FULLM, accA.x, off);
            accA.y += __shfl_xor_sync(FULLM, accA.y, off);
            accA.z += __shfl_xor_sync(FULLM, accA.z, off);
            accA.w += __shfl_xor_sync(FULLM, accA.w, off);
        }
        if (grp == 0) agg4[i * ROWF4 + r] = accA;
    }
}

// ---------------- MLP + BN stats: z = relu(agg@W1+b1)@W2+b2 -----------------
template <int STRIDE>
__global__ __launch_bounds__(256) void k_mlp(
    const float* __restrict__ agg, float* __restrict__ z_out,
    const float* __restrict__ W1, int w1rows, const float* __restrict__ b1,
    const float* __restrict__ W2, const float* __restrict__ b2, int layer)
{
    __shared__ float hs[8][32];
    __shared__ float rs[8][32], rq[8][32];

    int tid = threadIdx.x;
    int lane = tid & 31, wid = tid >> 5;

    float w1r[STRIDE], w2r[32];
#pragma unroll
    for (int c = 0; c < STRIDE; c++)
        w1r[c] = (c < w1rows) ? __ldg(&W1[c * 32 + lane]) : 0.f;
#pragma unroll
    for (int c = 0; c < 32; c++)
        w2r[c] = __ldg(&W2[c * 32 + lane]);
    float b1v = __ldg(&b1[lane]);
    float b2v = __ldg(&b2[lane]);

    int w  = blockIdx.x * (blockDim.x >> 5) + wid;
    int nw = gridDim.x * (blockDim.x >> 5);
    float ssum = 0.f, ssq = 0.f;

    const float4* agg4 = (const float4*)agg;

    for (int i = w; i < NN; i += nw) {
        float hid = b1v;
#pragma unroll
        for (int q = 0; q < STRIDE / 4; q++) {
            float4 a = __ldg(&agg4[i * (STRIDE / 4) + q]);
            hid = fmaf(a.x, w1r[4 * q + 0], hid);
            hid = fmaf(a.y, w1r[4 * q + 1], hid);
            hid = fmaf(a.z, w1r[4 * q + 2], hid);
            hid = fmaf(a.w, w1r[4 * q + 3], hid);
        }
        hid = fmaxf(hid, 0.f);

        hs[wid][lane] = hid;
        __syncwarp();
        float o = b2v;
        const float4* hrow = (const float4*)&hs[wid][0];
#pragma unroll
        for (int q = 0; q < 8; q++) {
            float4 hq = hrow[q];
            o = fmaf(hq.x, w2r[4 * q + 0], o);
            o = fmaf(hq.y, w2r[4 * q + 1], o);
            o = fmaf(hq.z, w2r[4 * q + 2], o);
            o = fmaf(hq.w, w2r[4 * q + 3], o);
        }
        __syncwarp();
        z_out[i * 32 + lane] = o;
        ssum += o;
        ssq  = fmaf(o, o, ssq);
    }

    rs[wid][lane] = ssum;
    rq[wid][lane] = ssq;
    __syncthreads();
    if (wid == 0) {
        float s = 0.f, q = 0.f;
#pragma unroll
        for (int ww = 0; ww < 8; ww++) { s += rs[ww][lane]; q += rq[ww][lane]; }
        atomicAdd(&g_stats[layer * 64 + lane], s);
        atomicAdd(&g_stats[layer * 64 + 32 + lane], q);
    }
}

// ---------------- BN apply + ReLU + incremental final linear ----------------
__global__ __launch_bounds__(256) void k_bn(
    const float* __restrict__ z, float* __restrict__ h_out,
    const float* __restrict__ gamma, const float* __restrict__ beta,
    const float* __restrict__ linW, const float* __restrict__ lin_b,
    int layer, int write_h)
{
    __shared__ float sc[32], bi[32], lw[256];
    int tid = threadIdx.x;
    if (tid < 32) {
        float s = g_stats[layer * 64 + tid];
        float q = g_stats[layer * 64 + 32 + tid];
        float mu  = s * (1.0f / NN);
        float var = q * (1.0f / NN) - mu * mu;
        float inv = rsqrtf(var + 1e-5f);
        float g = gamma[layer * 32 + tid] * inv;
        sc[tid] = g;
        bi[tid] = beta[layer * 32 + tid] - mu * g;
    }
    for (int i = tid; i < 256; i += blockDim.x) lw[i] = linW[layer * 256 + i];
    __syncthreads();

    int lane = tid & 31, wid = tid >> 5;
    int w  = blockIdx.x * (blockDim.x >> 5) + wid;
    int nw = gridDim.x * (blockDim.x >> 5);
    for (int i = w; i < NN; i += nw) {
        float zv = z[i * 32 + lane];
        float h = fmaxf(fmaf(zv, sc[lane], bi[lane]), 0.f);
        if (write_h) h_out[i * 32 + lane] = h;
        float od[8];
#pragma unroll
        for (int d = 0; d < 8; d++) {
            float p = h * lw[lane * 8 + d];
#pragma unroll
            for (int off = 16; off; off >>= 1)
                p += __shfl_xor_sync(FULLM, p, off);
            od[d] = p;
        }
        if (lane < 8) {
            float v = od[lane];
            if (layer == 0) v += lin_b[lane];
            else            v += g_acc[i * 8 + lane];
            g_acc[i * 8 + lane] = v;
        }
    }
}

// ---------------- masked write-back (masks are int32), float4 per node -----
__global__ void k_mask(const float* __restrict__ x,
                       const int* __restrict__ nm,
                       const int* __restrict__ em,
                       float* __restrict__ out)
{
    int i = blockIdx.x * blockDim.x + threadIdx.x;
    if (i < NN) {
        const float4* x4 = (const float4*)x;
        const float4* a4 = (const float4*)g_acc;
        float4* o4 = (float4*)out;
        float4 xlo = __ldg(&x4[i * 2 + 0]);
        float4 xhi = __ldg(&x4[i * 2 + 1]);
        float4 alo = a4[i * 2 + 0];
        float4 ahi = a4[i * 2 + 1];
        bool n = (nm[i] != 0), e = (em[i] != 0);
        bool w14 = n || e;   // cols 1..4
        bool w5  = n;        // col 5
        float4 olo = xlo, ohi = xhi;
        if (w14) { olo.y = alo.y; olo.z = alo.z; olo.w = alo.w; ohi.x = ahi.x; }
        if (w5)  { ohi.y = ahi.y; }
        o4[i * 2 + 0] = olo;
        o4[i * 2 + 1] = ohi;
    }
}

// ---------------- launch ----------------
extern "C" void kernel_launch(void* const* d_in, const int* in_sizes, int n_in,
                              void* d_out, int out_size)
{
    const float* x        = (const float*)d_in[0];
    const float* t        = (const float*)d_in[1];
    const int*   ei       = (const int*)d_in[2];
    const int*   node_mask = (const int*)d_in[3];
    const int*   edge_mask = (const int*)d_in[4];
    const float* W1_first = (const float*)d_in[7];
    const float* b1_first = (const float*)d_in[8];
    const float* W2_first = (const float*)d_in[9];
    const float* b2_first = (const float*)d_in[10];
    const float* W1_rest  = (const float*)d_in[11];
    const float* b1_rest  = (const float*)d_in[12];
    const float* W2_rest  = (const float*)d_in[13];
    const float* b2_rest  = (const float*)d_in[14];
    const float* eps      = (const float*)d_in[15];
    const float* bn_gamma = (const float*)d_in[16];
    const float* bn_beta  = (const float*)d_in[17];
    const float* lin_W    = (const float*)d_in[18];
    const float* lin_b    = (const float*)d_in[19];
    float* out = (float*)d_out;

    const int GB = 148 * 8;

    float* ag; cudaGetSymbolAddress((void**)&ag, g_agg);
    float* zz; cudaGetSymbolAddress((void**)&zz, g_z);
    float* hA; cudaGetSymbolAddress((void**)&hA, g_hA);
    float* hB; cudaGetSymbolAddress((void**)&hB, g_hB);

    k_hist<<<(EE + 255) / 256, 256>>>(ei);            // #0
    k_scan<<<256, 1024>>>();                          // #1 (fused 2-level scan)
    k_fill<<<(EE + 255) / 256, 256>>>(ei);            // #2
    k_agg0<<<GB, 256>>>(x, ag, eps, t);               // #3  <- ncu captures this
    k_mlp<16><<<GB, 256>>>(ag, zz, W1_first, 9, b1_first, W2_first, b2_first, 0);
    k_bn<<<GB, 256>>>(zz, hA, bn_gamma, bn_beta, lin_W, lin_b, 0, 1);

    // Layer 1
    k_agg<<<GB, 256>>>(hA, ag, eps, 1);
    k_mlp<32><<<GB, 256>>>(ag, zz, W1_rest + 0 * 1024, 32, b1_rest + 0 * 32,
                           W2_rest + 0 * 1024, b2_rest + 0 * 32, 1);
    k_bn<<<GB, 256>>>(zz, hB, bn_gamma, bn_beta, lin_W, lin_b, 1, 1);

    // Layer 2
    k_agg<<<GB, 256>>>(hB, ag, eps, 2);
    k_mlp<32><<<GB, 256>>>(ag, zz, W1_rest + 1 * 1024, 32, b1_rest + 1 * 32,
                           W2_rest + 1 * 1024, b2_rest + 1 * 32, 2);
    k_bn<<<GB, 256>>>(zz, hA, bn_gamma, bn_beta, lin_W, lin_b, 2, 1);

    // Layer 3 (h never consumed afterward -> skip h store)
    k_agg<<<GB, 256>>>(hA, ag, eps, 3);
    k_mlp<32><<<GB, 256>>>(ag, zz, W1_rest + 2 * 1024, 32, b1_rest + 2 * 32,
                           W2_rest + 2 * 1024, b2_rest + 2 * 32, 3);
    k_bn<<<GB, 256>>>(zz, hB, bn_gamma, bn_beta, lin_W, lin_b, 3, 0);

    k_mask<<<(NN + 255) / 256, 256>>>(x, node_mask, edge_mask, out);
}

// round 11
// speedup vs baseline: 1.2704x; 1.0507x over previous
#include <cuda_runtime.h>

// Problem constants (fixed by the reference setup)
#define NN 262144
#define EE 4194304
#define HID 32
#define LYR 4
#define FULLM 0xffffffffu

typedef unsigned long long ull;

// packed f32x2 helpers (sm_103a)
#define ADDX2(out, a, b) \
    asm("add.rn.f32x2 %0, %1, %2;" : "=l"(out) : "l"(a), "l"(b))
#define MULX2(out, a, b) \
    asm("mul.rn.f32x2 %0, %1, %2;" : "=l"(out) : "l"(a), "l"(b))
#define FMAX2(out, a, b, c) \
    asm("fma.rn.f32x2 %0, %1, %2, %3;" : "=l"(out) : "l"(a), "l"(b), "l"(c))
#define PACKX2(out, lo, hi) \
    asm("mov.b64 %0, {%1, %2};" : "=l"(out) : "f"(lo), "f"(hi))
#define UNPACKX2(lo, hi, in) \
    asm("mov.b64 {%0, %1}, %2;" : "=f"(lo), "=f"(hi) : "l"(in))

// ---------------- device scratch (static, no allocation) ----------------
__device__ int   g_deg[NN];        // zeroed at module load; re-zeroed by k_scan
__device__ int   g_cursor[NN];     // block-local offsets; after fill: local ends
__device__ int   g_blocksum[256];
__device__ int   g_boff[256];      // exclusive prefix of block sums
__device__ int   g_tick;           // last-block ticket (reset each run)
__device__ int   g_csr[EE];
__device__ __align__(16) float g_agg[NN * 32];
__device__ __align__(16) float g_z[NN * 32];
__device__ __align__(16) float g_hA[NN * 32];
__device__ __align__(16) float g_hB[NN * 32];
__device__ __align__(16) float g_acc[NN * 8];
__device__ float g_stats[LYR * 64];

// ---------------- #0: degree histogram ----------------
__global__ void k_hist(const int* __restrict__ ei) {
    int e = blockIdx.x * blockDim.x + threadIdx.x;
    if (e < EE) atomicAdd(&g_deg[ei[EE + e]], 1);
}

// ---------------- #1: fused two-level scan (last-block pattern) ----------
__global__ void k_scan() {
    __shared__ int wt[32];
    __shared__ int s_tot;
    __shared__ bool s_last;
    int tid = threadIdx.x, lane = tid & 31, wid = tid >> 5;
    int g = blockIdx.x * 1024 + tid;
    int v = g_deg[g];
    g_deg[g] = 0;
    int xv = v;
#pragma unroll
    for (int off = 1; off < 32; off <<= 1) {
        int y = __shfl_up_sync(FULLM, xv, off);
        if (lane >= off) xv += y;
    }
    if (lane == 31) wt[wid] = xv;
    __syncthreads();
    if (wid == 0) {
        int w = wt[lane];
        int xi = w;
#pragma unroll
        for (int off = 1; off < 32; off <<= 1) {
            int y = __shfl_up_sync(FULLM, xi, off);
            if (lane >= off) xi += y;
        }
        wt[lane] = xi - w;
        if (lane == 31) s_tot = xi;
    }
    __syncthreads();
    g_cursor[g] = (xv - v) + wt[wid];

    if (tid == 0) {
        g_blocksum[blockIdx.x] = s_tot;
        __threadfence();
        s_last = (atomicAdd(&g_tick, 1) == 255);
    }
    __syncthreads();
    if (s_last) {
        __shared__ int wt2[8];
        int bv = (tid < 256) ? g_blocksum[tid] : 0;
        int xi = bv;
#pragma unroll
        for (int off = 1; off < 32; off <<= 1) {
            int y = __shfl_up_sync(FULLM, xi, off);
            if (lane >= off) xi += y;
        }
        if (tid < 256 && lane == 31) wt2[wid] = xi;
        __syncthreads();
        if (tid == 0) {
            int s = 0;
            for (int k = 0; k < 8; k++) { int t0 = wt2[k]; wt2[k] = s; s += t0; }
        }
        __syncthreads();
        if (tid < 256) {
            g_boff[tid] = (xi - bv) + wt2[wid];
            g_stats[tid] = 0.f;
        }
        if (tid == 0) g_tick = 0;
    }
}

// ---------------- #2: CSR fill ----------------
__global__ void k_fill(const int* __restrict__ ei) {
    int e = blockIdx.x * blockDim.x + threadIdx.x;
    if (e < EE) {
        int d = ei[EE + e];
        int p = __ldg(&g_boff[d >> 10]) + atomicAdd(&g_cursor[d], 1);
        g_csr[p] = ei[e];
    }
}

// ---------------- #3 (ncu capture slot): layer-0 aggregation --------------
// Packed f32x2 accumulate. x rows 32B; agg stride 16 floats.
__global__ __launch_bounds__(256) void k_agg0(
    const float* __restrict__ x, float* __restrict__ agg_out,
    const float* __restrict__ eps_p, const float* __restrict__ tptr)
{
    float epsv = 1.0f + eps_p[0];
    ull epsv2; PACKX2(epsv2, epsv, epsv);
    float tv = tptr[0];
    int tid = threadIdx.x, lane = tid & 31, wid = tid >> 5;
    int grp = lane >> 1, r = lane & 1;
    int w  = blockIdx.x * (blockDim.x >> 5) + wid;
    int nw = gridDim.x * (blockDim.x >> 5);
    const ulonglong2* x2 = (const ulonglong2*)x;
    ulonglong2* agg2 = (ulonglong2*)agg_out;

    for (int i = w; i < NN; i += nw) {
        int bo = __ldg(&g_boff[i >> 10]);
        int le = g_cursor[i];
        int ls = (i & 1023) ? g_cursor[i - 1] : 0;
        int start = bo + ls, end = bo + le;

        ulonglong2 accA, accB;
        accB.x = accB.y = 0ull;
        if (grp == 0) {
            ulonglong2 s = __ldg(&x2[i * 2 + r]);
            MULX2(accA.x, s.x, epsv2);
            MULX2(accA.y, s.y, epsv2);
        } else {
            accA.x = accA.y = 0ull;
        }

        for (int j0 = start; j0 < end; j0 += 32) {
            int myj = j0 + lane;
            int idx = (myj < end) ? g_csr[myj] : 0;
            int cnt = min(32, end - j0);
            int k = 0;
            for (; k + 32 <= cnt; k += 32) {
                int s0 = __shfl_sync(FULLM, idx, k + grp);
                int s1 = __shfl_sync(FULLM, idx, k + 16 + grp);
                ulonglong2 v0 = __ldg(&x2[s0 * 2 + r]);
                ulonglong2 v1 = __ldg(&x2[s1 * 2 + r]);
                ADDX2(accA.x, accA.x, v0.x); ADDX2(accA.y, accA.y, v0.y);
                ADDX2(accB.x, accB.x, v1.x); ADDX2(accB.y, accB.y, v1.y);
            }
            for (; k < cnt; k += 16) {
                int e2 = k + grp;
                int s = __shfl_sync(FULLM, idx, e2 & 31);
                if (e2 < cnt) {
                    ulonglong2 v = __ldg(&x2[s * 2 + r]);
                    ADDX2(accA.x, accA.x, v.x); ADDX2(accA.y, accA.y, v.y);
                }
            }
        }
        ADDX2(accA.x, accA.x, accB.x);
        ADDX2(accA.y, accA.y, accB.y);
#pragma unroll
        for (int off = 2; off < 32; off <<= 1) {
            ull tx = __shfl_xor_sync(FULLM, accA.x, off);
            ull ty = __shfl_xor_sync(FULLM, accA.y, off);
            ADDX2(accA.x, accA.x, tx);
            ADDX2(accA.y, accA.y, ty);
        }
        if (grp == 0) {
            agg2[i * 4 + r] = accA;
        } else if (grp == 1) {
            float tt = (epsv + (float)(end - start)) * tv;
            ulonglong2 tvv;
            if (r == 0) { PACKX2(tvv.x, tt, 0.f); } else { tvv.x = 0ull; }
            tvv.y = 0ull;
            agg2[i * 4 + 2 + r] = tvv;
        }
    }
}

// ---------------- aggregation for layers 1..3 (32-float rows) -------------
__global__ __launch_bounds__(256) void k_agg(
    const float* __restrict__ h_in, float* __restrict__ agg_out,
    const float* __restrict__ eps_p, int layer)
{
    float epsv = 1.0f + eps_p[layer];
    ull epsv2; PACKX2(epsv2, epsv, epsv);

    int tid = threadIdx.x, lane = tid & 31, wid = tid >> 5;
    int grp  = lane >> 3;            // 4 groups of 8 lanes
    int r    = lane & 7;             // ulonglong2 slot within row (8 x 16B)
    int w  = blockIdx.x * (blockDim.x >> 5) + wid;
    int nw = gridDim.x * (blockDim.x >> 5);

    const ulonglong2* hin2 = (const ulonglong2*)h_in;
    ulonglong2* agg2 = (ulonglong2*)agg_out;

    for (int i = w; i < NN; i += nw) {
        int bo = __ldg(&g_boff[i >> 10]);
        int le = g_cursor[i];
        int ls = (i & 1023) ? g_cursor[i - 1] : 0;
        int start = bo + ls, end = bo + le;

        ulonglong2 accA, accB;
        accB.x = accB.y = 0ull;
        if (grp == 0) {
            ulonglong2 s = __ldg(&hin2[i * 8 + r]);
            MULX2(accA.x, s.x, epsv2);
            MULX2(accA.y, s.y, epsv2);
        } else {
            accA.x = accA.y = 0ull;
        }

        for (int j0 = start; j0 < end; j0 += 32) {
            int myj = j0 + lane;
            int idx = (myj < end) ? g_csr[myj] : 0;
            int cnt = min(32, end - j0);
            int k = 0;
            for (; k + 8 <= cnt; k += 8) {
                int s0 = __shfl_sync(FULLM, idx, k + grp);
                int s1 = __shfl_sync(FULLM, idx, k + 4 + grp);
                ulonglong2 v0 = __ldg(&hin2[s0 * 8 + r]);
                ulonglong2 v1 = __ldg(&hin2[s1 * 8 + r]);
                ADDX2(accA.x, accA.x, v0.x); ADDX2(accA.y, accA.y, v0.y);
                ADDX2(accB.x, accB.x, v1.x); ADDX2(accB.y, accB.y, v1.y);
            }
            for (; k < cnt; k += 4) {
                int e2 = k + grp;
                int s = __shfl_sync(FULLM, idx, e2 & 31);
                if (e2 < cnt) {
                    ulonglong2 v = __ldg(&hin2[s * 8 + r]);
                    ADDX2(accA.x, accA.x, v.x); ADDX2(accA.y, accA.y, v.y);
                }
            }
        }
        ADDX2(accA.x, accA.x, accB.x);
        ADDX2(accA.y, accA.y, accB.y);
#pragma unroll
        for (int off = 8; off < 32; off <<= 1) {
            ull tx = __shfl_xor_sync(FULLM, accA.x, off);
            ull ty = __shfl_xor_sync(FULLM, accA.y, off);
            ADDX2(accA.x, accA.x, tx);
            ADDX2(accA.y, accA.y, ty);
        }
        if (grp == 0) agg2[i * 8 + r] = accA;
    }
}

// ---------------- MLP + BN stats: z = relu(agg@W1+b1)@W2+b2 -----------------
// Packed-fma matvecs; weight pairs in registers.
template <int STRIDE>
__global__ __launch_bounds__(256) void k_mlp(
    const float* __restrict__ agg, float* __restrict__ z_out,
    const float* __restrict__ W1, int w1rows, const float* __restrict__ b1,
    const float* __restrict__ W2, const float* __restrict__ b2, int layer)
{
    __shared__ __align__(16) float hs[8][32];
    __shared__ float rs[8][32], rq[8][32];

    int tid = threadIdx.x;
    int lane = tid & 31, wid = tid >> 5;

    ull w1p[STRIDE / 2], w2p[16];
#pragma unroll
    for (int c = 0; c < STRIDE; c += 2) {
        float a = (c     < w1rows) ? __ldg(&W1[c * 32 + lane])       : 0.f;
        float b = (c + 1 < w1rows) ? __ldg(&W1[(c + 1) * 32 + lane]) : 0.f;
        PACKX2(w1p[c / 2], a, b);
    }
#pragma unroll
    for (int c = 0; c < 32; c += 2) {
        float a = __ldg(&W2[c * 32 + lane]);
        float b = __ldg(&W2[(c + 1) * 32 + lane]);
        PACKX2(w2p[c / 2], a, b);
    }
    float b1v = __ldg(&b1[lane]);
    float b2v = __ldg(&b2[lane]);

    int w  = blockIdx.x * (blockDim.x >> 5) + wid;
    int nw = gridDim.x * (blockDim.x >> 5);
    float ssum = 0.f, ssq = 0.f;

    const ulonglong2* agg2 = (const ulonglong2*)agg;

    for (int i = w; i < NN; i += nw) {
        ull hp0 = 0ull, hp1 = 0ull;
#pragma unroll
        for (int q = 0; q < STRIDE / 4; q++) {
            ulonglong2 a = __ldg(&agg2[i * (STRIDE / 4) + q]);
            FMAX2(hp0, a.x, w1p[2 * q + 0], hp0);
            FMAX2(hp1, a.y, w1p[2 * q + 1], hp1);
        }
        ADDX2(hp0, hp0, hp1);
        float lo, hi; UNPACKX2(lo, hi, hp0);
        float hid = fmaxf(b1v + lo + hi, 0.f);

        hs[wid][lane] = hid;
        __syncwarp();
        ull op0 = 0ull, op1 = 0ull;
        const ulonglong2* hrow = (const ulonglong2*)&hs[wid][0];
#pragma unroll
        for (int q = 0; q < 8; q++) {
            ulonglong2 hq = hrow[q];
            FMAX2(op0, hq.x, w2p[2 * q + 0], op0);
            FMAX2(op1, hq.y, w2p[2 * q + 1], op1);
        }
        __syncwarp();
        ADDX2(op0, op0, op1);
        float ol, oh; UNPACKX2(ol, oh, op0);
        float o = b2v + ol + oh;
        z_out[i * 32 + lane] = o;
        ssum += o;
        ssq  = fmaf(o, o, ssq);
    }

    rs[wid][lane] = ssum;
    rq[wid][lane] = ssq;
    __syncthreads();
    if (wid == 0) {
        float s = 0.f, q = 0.f;
#pragma unroll
        for (int ww = 0; ww < 8; ww++) { s += rs[ww][lane]; q += rq[ww][lane]; }
        atomicAdd(&g_stats[layer * 64 + lane], s);
        atomicAdd(&g_stats[layer * 64 + 32 + lane], q);
    }
}

// ---------------- BN apply + ReLU + incremental final linear ----------------
// od via smem-h broadcast + packed fma with lin_W column in registers.
__global__ __launch_bounds__(256) void k_bn(
    const float* __restrict__ z, float* __restrict__ h_out,
    const float* __restrict__ gamma, const float* __restrict__ beta,
    const float* __restrict__ linW, const float* __restrict__ lin_b,
    int layer, int write_h)
{
    __shared__ float sc[32], bi[32];
    __shared__ __align__(16) float hsm[8][32];
    int tid = threadIdx.x;
    int lane = tid & 31, wid = tid >> 5;
    if (tid < 32) {
        float s = g_stats[layer * 64 + tid];
        float q = g_stats[layer * 64 + 32 + tid];
        float mu  = s * (1.0f / NN);
        float var = q * (1.0f / NN) - mu * mu;
        float inv = rsqrtf(var + 1e-5f);
        float g = gamma[layer * 32 + tid] * inv;
        sc[tid] = g;
        bi[tid] = beta[layer * 32 + tid] - mu * g;
    }
    // lin_W column for dim d = lane&7, packed over channel pairs
    int myd = lane & 7;
    ull lwp[16];
#pragma unroll
    for (int c = 0; c < 32; c += 2) {
        float a = __ldg(&linW[layer * 256 + c * 8 + myd]);
        float b = __ldg(&linW[layer * 256 + (c + 1) * 8 + myd]);
        PACKX2(lwp[c / 2], a, b);
    }
    float lbv = __ldg(&lin_b[myd]);
    __syncthreads();

    int w  = blockIdx.x * (blockDim.x >> 5) + wid;
    int nw = gridDim.x * (blockDim.x >> 5);
    for (int i = w; i < NN; i += nw) {
        float zv = z[i * 32 + lane];
        float h = fmaxf(fmaf(zv, sc[lane], bi[lane]), 0.f);
        if (write_h) h_out[i * 32 + lane] = h;
        hsm[wid][lane] = h;
        __syncwarp();
        ull op0 = 0ull, op1 = 0ull;
        const ulonglong2* hrow = (const ulonglong2*)&hsm[wid][0];
#pragma unroll
        for (int q = 0; q < 8; q++) {
            ulonglong2 hq = hrow[q];
            FMAX2(op0, hq.x, lwp[2 * q + 0], op0);
            FMAX2(op1, hq.y, lwp[2 * q + 1], op1);
        }
        __syncwarp();
        ADDX2(op0, op0, op1);
        float ol, oh; UNPACKX2(ol, oh, op0);
        float v = ol + oh;
        if (lane < 8) {
            if (layer == 0) v += lbv;
            else            v += g_acc[i * 8 + lane];
            g_acc[i * 8 + lane] = v;
        }
    }
}

// ---------------- masked write-back (masks are int32), float4 per node -----
__global__ void k_mask(const float* __restrict__ x,
                       const int* __restrict__ nm,
                       const int* __restrict__ em,
                       float* __restrict__ out)
{
    int i = blockIdx.x * blockDim.x + threadIdx.x;
    if (i < NN) {
        const float4* x4 = (const float4*)x;
        const float4* a4 = (const float4*)g_acc;
        float4* o4 = (float4*)out;
        float4 xlo = __ldg(&x4[i * 2 + 0]);
        float4 xhi = __ldg(&x4[i * 2 + 1]);
        float4 alo = a4[i * 2 + 0];
        float4 ahi = a4[i * 2 + 1];
        bool n = (nm[i] != 0), e = (em[i] != 0);
        bool w14 = n || e;   // cols 1..4
        bool w5  = n;        // col 5
        float4 olo = xlo, ohi = xhi;
        if (w14) { olo.y = alo.y; olo.z = alo.z; olo.w = alo.w; ohi.x = ahi.x; }
        if (w5)  { ohi.y = ahi.y; }
        o4[i * 2 + 0] = olo;
        o4[i * 2 + 1] = ohi;
    }
}

// ---------------- launch ----------------
extern "C" void kernel_launch(void* const* d_in, const int* in_sizes, int n_in,
                              void* d_out, int out_size)
{
    const float* x        = (const float*)d_in[0];
    const float* t        = (const float*)d_in[1];
    const int*   ei       = (const int*)d_in[2];
    const int*   node_mask = (const int*)d_in[3];
    const int*   edge_mask = (const int*)d_in[4];
    const float* W1_first = (const float*)d_in[7];
    const float* b1_first = (const float*)d_in[8];
    const float* W2_first = (const float*)d_in[9];
    const float* b2_first = (const float*)d_in[10];
    const float* W1_rest  = (const float*)d_in[11];
    const float* b1_rest  = (const float*)d_in[12];
    const float* W2_rest  = (const float*)d_in[13];
    const float* b2_rest  = (const float*)d_in[14];
    const float* eps      = (const float*)d_in[15];
    const float* bn_gamma = (const float*)d_in[16];
    const float* bn_beta  = (const float*)d_in[17];
    const float* lin_W    = (const float*)d_in[18];
    const float* lin_b    = (const float*)d_in[19];
    float* out = (float*)d_out;

    const int GB = 148 * 8;

    float* ag; cudaGetSymbolAddress((void**)&ag, g_agg);
    float* zz; cudaGetSymbolAddress((void**)&zz, g_z);
    float* hA; cudaGetSymbolAddress((void**)&hA, g_hA);
    float* hB; cudaGetSymbolAddress((void**)&hB, g_hB);

    k_hist<<<(EE + 255) / 256, 256>>>(ei);            // #0
    k_scan<<<256, 1024>>>();                          // #1
    k_fill<<<(EE + 255) / 256, 256>>>(ei);            // #2
    k_agg0<<<GB, 256>>>(x, ag, eps, t);               // #3  <- ncu captures this
    k_mlp<16><<<GB, 256>>>(ag, zz, W1_first, 9, b1_first, W2_first, b2_first, 0);
    k_bn<<<GB, 256>>>(zz, hA, bn_gamma, bn_beta, lin_W, lin_b, 0, 1);

    // Layer 1
    k_agg<<<GB, 256>>>(hA, ag, eps, 1);
    k_mlp<32><<<GB, 256>>>(ag, zz, W1_rest + 0 * 1024, 32, b1_rest + 0 * 32,
                           W2_rest + 0 * 1024, b2_rest + 0 * 32, 1);
    k_bn<<<GB, 256>>>(zz, hB, bn_gamma, bn_beta, lin_W, lin_b, 1, 1);

    // Layer 2
    k_agg<<<GB, 256>>>(hB, ag, eps, 2);
    k_mlp<32><<<GB, 256>>>(ag, zz, W1_rest + 1 * 1024, 32, b1_rest + 1 * 32,
                           W2_rest + 1 * 1024, b2_rest + 1 * 32, 2);
    k_bn<<<GB, 256>>>(zz, hA, bn_gamma, bn_beta, lin_W, lin_b, 2, 1);

    // Layer 3 (h never consumed afterward -> skip h store)
    k_agg<<<GB, 256>>>(hA, ag, eps, 3);
    k_mlp<32><<<GB, 256>>>(ag, zz, W1_rest + 2 * 1024, 32, b1_rest + 2 * 32,
                           W2_rest + 2 * 1024, b2_rest + 2 * 32, 3);
    k_bn<<<GB, 256>>>(zz, hB, bn_gamma, bn_beta, lin_W, lin_b, 3, 0);

    k_mask<<<(NN + 255) / 256, 256>>>(x, node_mask, edge_mask, out);
}

// round 12
// speedup vs baseline: 1.2822x; 1.0093x over previous
#include <cuda_runtime.h>

// Problem constants (fixed by the reference setup)
#define NN 262144
#define EE 4194304
#define HID 32
#define LYR 4
#define FULLM 0xffffffffu

typedef unsigned long long ull;

// packed f32x2 helpers (sm_103a)
#define ADDX2(out, a, b) \
    asm("add.rn.f32x2 %0, %1, %2;" : "=l"(out) : "l"(a), "l"(b))
#define MULX2(out, a, b) \
    asm("mul.rn.f32x2 %0, %1, %2;" : "=l"(out) : "l"(a), "l"(b))
#define FMAX2(out, a, b, c) \
    asm("fma.rn.f32x2 %0, %1, %2, %3;" : "=l"(out) : "l"(a), "l"(b), "l"(c))
#define PACKX2(out, lo, hi) \
    asm("mov.b64 %0, {%1, %2};" : "=l"(out) : "f"(lo), "f"(hi))
#define UNPACKX2(lo, hi, in) \
    asm("mov.b64 {%0, %1}, %2;" : "=f"(lo), "=f"(hi) : "l"(in))

// ---------------- device scratch (static, no allocation) ----------------
__device__ int   g_deg[NN];        // zeroed at module load; re-zeroed by k_scan
__device__ int   g_cursor[NN];     // block-local offsets; after fill: local ends
__device__ int   g_blocksum[256];
__device__ int   g_boff[256];      // exclusive prefix of block sums
__device__ int   g_tick;           // last-block ticket (reset each run)
__device__ int   g_csr[EE];
__device__ __align__(16) float g_agg[NN * 32];
__device__ __align__(16) float g_z[NN * 32];
__device__ __align__(16) float g_hA[NN * 32];
__device__ __align__(16) float g_hB[NN * 32];
__device__ __align__(16) float g_acc[NN * 8];
__device__ float g_stats[LYR * 64];

// ---------------- #0: degree histogram ----------------
__global__ void k_hist(const int* __restrict__ ei) {
    int e = blockIdx.x * blockDim.x + threadIdx.x;
    if (e < EE) atomicAdd(&g_deg[ei[EE + e]], 1);
}

// ---------------- #1: fused two-level scan (last-block pattern) ----------
__global__ void k_scan() {
    __shared__ int wt[32];
    __shared__ int s_tot;
    __shared__ bool s_last;
    int tid = threadIdx.x, lane = tid & 31, wid = tid >> 5;
    int g = blockIdx.x * 1024 + tid;
    int v = g_deg[g];
    g_deg[g] = 0;
    int xv = v;
#pragma unroll
    for (int off = 1; off < 32; off <<= 1) {
        int y = __shfl_up_sync(FULLM, xv, off);
        if (lane >= off) xv += y;
    }
    if (lane == 31) wt[wid] = xv;
    __syncthreads();
    if (wid == 0) {
        int w = wt[lane];
        int xi = w;
#pragma unroll
        for (int off = 1; off < 32; off <<= 1) {
            int y = __shfl_up_sync(FULLM, xi, off);
            if (lane >= off) xi += y;
        }
        wt[lane] = xi - w;
        if (lane == 31) s_tot = xi;
    }
    __syncthreads();
    g_cursor[g] = (xv - v) + wt[wid];

    if (tid == 0) {
        g_blocksum[blockIdx.x] = s_tot;
        __threadfence();
        s_last = (atomicAdd(&g_tick, 1) == 255);
    }
    __syncthreads();
    if (s_last) {
        __shared__ int wt2[8];
        int bv = (tid < 256) ? g_blocksum[tid] : 0;
        int xi = bv;
#pragma unroll
        for (int off = 1; off < 32; off <<= 1) {
            int y = __shfl_up_sync(FULLM, xi, off);
            if (lane >= off) xi += y;
        }
        if (tid < 256 && lane == 31) wt2[wid] = xi;
        __syncthreads();
        if (tid == 0) {
            int s = 0;
            for (int k = 0; k < 8; k++) { int t0 = wt2[k]; wt2[k] = s; s += t0; }
        }
        __syncthreads();
        if (tid < 256) {
            g_boff[tid] = (xi - bv) + wt2[wid];
            g_stats[tid] = 0.f;
        }
        if (tid == 0) g_tick = 0;
    }
}

// ---------------- #2: CSR fill ----------------
__global__ void k_fill(const int* __restrict__ ei) {
    int e = blockIdx.x * blockDim.x + threadIdx.x;
    if (e < EE) {
        int d = ei[EE + e];
        int p = __ldg(&g_boff[d >> 10]) + atomicAdd(&g_cursor[d], 1);
        g_csr[p] = ei[e];
    }
}

// ---------------- #3 (ncu capture slot): layer-0 aggregation --------------
// Group-per-node: 2-lane group owns one node (16 nodes/warp). No fold.
__global__ __launch_bounds__(256) void k_agg0(
    const float* __restrict__ x, float* __restrict__ agg_out,
    const float* __restrict__ eps_p, const float* __restrict__ tptr)
{
    float epsv = 1.0f + eps_p[0];
    ull epsv2; PACKX2(epsv2, epsv, epsv);
    float tv = tptr[0];
    int tid = threadIdx.x, lane = tid & 31, wid = tid >> 5;
    int g = lane >> 1;               // node sub-index 0..15
    int r = lane & 1;                // 16B slot within 32B row
    int w  = blockIdx.x * (blockDim.x >> 5) + wid;
    int nw = gridDim.x * (blockDim.x >> 5);
    const ulonglong2* x2 = (const ulonglong2*)x;
    ulonglong2* agg2 = (ulonglong2*)agg_out;

    for (int tile = w; tile < NN / 16; tile += nw) {
        int i = tile * 16 + g;
        int bo = __ldg(&g_boff[i >> 10]);
        int le = g_cursor[i];
        int ls = (i & 1023) ? g_cursor[i - 1] : 0;
        int start = bo + ls;
        int deg = le - ls;

        int md = deg;
#pragma unroll
        for (int off = 16; off >= 2; off >>= 1)
            md = max(md, __shfl_xor_sync(FULLM, md, off));

        ull a0 = 0ull, a1 = 0ull, b0 = 0ull, b1 = 0ull;
        for (int j = 0; j < md; j += 2) {
            bool p0 = (j < deg), p1 = (j + 1 < deg);
            int s0 = 0, s1 = 0;
            if (p0) s0 = __ldg(&g_csr[start + j]);
            if (p1) s1 = __ldg(&g_csr[start + j + 1]);
            ull v0x = 0ull, v0y = 0ull, v1x = 0ull, v1y = 0ull;
            if (p0) { ulonglong2 v = __ldg(&x2[s0 * 2 + r]); v0x = v.x; v0y = v.y; }
            if (p1) { ulonglong2 v = __ldg(&x2[s1 * 2 + r]); v1x = v.x; v1y = v.y; }
            ADDX2(a0, a0, v0x); ADDX2(a1, a1, v0y);
            ADDX2(b0, b0, v1x); ADDX2(b1, b1, v1y);
        }
        ADDX2(a0, a0, b0);
        ADDX2(a1, a1, b1);
        // self term
        ulonglong2 sf = __ldg(&x2[i * 2 + r]);
        FMAX2(a0, sf.x, epsv2, a0);
        FMAX2(a1, sf.y, epsv2, a1);
        ulonglong2 res; res.x = a0; res.y = a1;
        agg2[i * 4 + r] = res;
        // t column (chunk 2) + zero pad (chunk 3)
        float tt = (epsv + (float)deg) * tv;
        ulonglong2 pad;
        if (r == 0) { PACKX2(pad.x, tt, 0.f); } else { pad.x = 0ull; }
        pad.y = 0ull;
        agg2[i * 4 + 2 + r] = pad;
    }
}

// ---------------- aggregation for layers 1..3 (128B rows) -----------------
// Group-per-node: 8-lane group owns one node (4 nodes/warp). One LDG = full
// rows of 4 edges; each L1 line touched once. No fold.
__global__ __launch_bounds__(256) void k_agg(
    const float* __restrict__ h_in, float* __restrict__ agg_out,
    const float* __restrict__ eps_p, int layer)
{
    float epsv = 1.0f + eps_p[layer];
    ull epsv2; PACKX2(epsv2, epsv, epsv);

    int tid = threadIdx.x, lane = tid & 31, wid = tid >> 5;
    int g = lane >> 3;               // node sub-index 0..3
    int r = lane & 7;                // 16B slot within 128B row
    int w  = blockIdx.x * (blockDim.x >> 5) + wid;
    int nw = gridDim.x * (blockDim.x >> 5);

    const ulonglong2* hin2 = (const ulonglong2*)h_in;
    ulonglong2* agg2 = (ulonglong2*)agg_out;

    for (int tile = w; tile < NN / 4; tile += nw) {
        int i = tile * 4 + g;
        int bo = __ldg(&g_boff[i >> 10]);
        int le = g_cursor[i];
        int ls = (i & 1023) ? g_cursor[i - 1] : 0;
        int start = bo + ls;
        int deg = le - ls;

        int md = deg;
#pragma unroll
        for (int off = 16; off >= 8; off >>= 1)
            md = max(md, __shfl_xor_sync(FULLM, md, off));

        ull a0 = 0ull, a1 = 0ull, b0 = 0ull, b1 = 0ull;
        for (int j = 0; j < md; j += 2) {
            bool p0 = (j < deg), p1 = (j + 1 < deg);
            int s0 = 0, s1 = 0;
            if (p0) s0 = __ldg(&g_csr[start + j]);
            if (p1) s1 = __ldg(&g_csr[start + j + 1]);
            ull v0x = 0ull, v0y = 0ull, v1x = 0ull, v1y = 0ull;
            if (p0) { ulonglong2 v = __ldg(&hin2[s0 * 8 + r]); v0x = v.x; v0y = v.y; }
            if (p1) { ulonglong2 v = __ldg(&hin2[s1 * 8 + r]); v1x = v.x; v1y = v.y; }
            ADDX2(a0, a0, v0x); ADDX2(a1, a1, v0y);
            ADDX2(b0, b0, v1x); ADDX2(b1, b1, v1y);
        }
        ADDX2(a0, a0, b0);
        ADDX2(a1, a1, b1);
        ulonglong2 sf = __ldg(&hin2[i * 8 + r]);
        FMAX2(a0, sf.x, epsv2, a0);
        FMAX2(a1, sf.y, epsv2, a1);
        ulonglong2 res; res.x = a0; res.y = a1;
        agg2[i * 8 + r] = res;
    }
}

// ---------------- MLP + BN stats: z = relu(agg@W1+b1)@W2+b2 -----------------
template <int STRIDE>
__global__ __launch_bounds__(256) void k_mlp(
    const float* __restrict__ agg, float* __restrict__ z_out,
    const float* __restrict__ W1, int w1rows, const float* __restrict__ b1,
    const float* __restrict__ W2, const float* __restrict__ b2, int layer)
{
    __shared__ __align__(16) float hs[8][32];
    __shared__ float rs[8][32], rq[8][32];

    int tid = threadIdx.x;
    int lane = tid & 31, wid = tid >> 5;

    ull w1p[STRIDE / 2], w2p[16];
#pragma unroll
    for (int c = 0; c < STRIDE; c += 2) {
        float a = (c     < w1rows) ? __ldg(&W1[c * 32 + lane])       : 0.f;
        float b = (c + 1 < w1rows) ? __ldg(&W1[(c + 1) * 32 + lane]) : 0.f;
        PACKX2(w1p[c / 2], a, b);
    }
#pragma unroll
    for (int c = 0; c < 32; c += 2) {
        float a = __ldg(&W2[c * 32 + lane]);
        float b = __ldg(&W2[(c + 1) * 32 + lane]);
        PACKX2(w2p[c / 2], a, b);
    }
    float b1v = __ldg(&b1[lane]);
    float b2v = __ldg(&b2[lane]);

    int w  = blockIdx.x * (blockDim.x >> 5) + wid;
    int nw = gridDim.x * (blockDim.x >> 5);
    float ssum = 0.f, ssq = 0.f;

    const ulonglong2* agg2 = (const ulonglong2*)agg;

    for (int i = w; i < NN; i += nw) {
        ull hp0 = 0ull, hp1 = 0ull;
#pragma unroll
        for (int q = 0; q < STRIDE / 4; q++) {
            ulonglong2 a = __ldg(&agg2[i * (STRIDE / 4) + q]);
            FMAX2(hp0, a.x, w1p[2 * q + 0], hp0);
            FMAX2(hp1, a.y, w1p[2 * q + 1], hp1);
        }
        ADDX2(hp0, hp0, hp1);
        float lo, hi; UNPACKX2(lo, hi, hp0);
        float hid = fmaxf(b1v + lo + hi, 0.f);

        hs[wid][lane] = hid;
        __syncwarp();
        ull op0 = 0ull, op1 = 0ull;
        const ulonglong2* hrow = (const ulonglong2*)&hs[wid][0];
#pragma unroll
        for (int q = 0; q < 8; q++) {
            ulonglong2 hq = hrow[q];
            FMAX2(op0, hq.x, w2p[2 * q + 0], op0);
            FMAX2(op1, hq.y, w2p[2 * q + 1], op1);
        }
        __syncwarp();
        ADDX2(op0, op0, op1);
        float ol, oh; UNPACKX2(ol, oh, op0);
        float o = b2v + ol + oh;
        z_out[i * 32 + lane] = o;
        ssum += o;
        ssq  = fmaf(o, o, ssq);
    }

    rs[wid][lane] = ssum;
    rq[wid][lane] = ssq;
    __syncthreads();
    if (wid == 0) {
        float s = 0.f, q = 0.f;
#pragma unroll
        for (int ww = 0; ww < 8; ww++) { s += rs[ww][lane]; q += rq[ww][lane]; }
        atomicAdd(&g_stats[layer * 64 + lane], s);
        atomicAdd(&g_stats[layer * 64 + 32 + lane], q);
    }
}

// ---------------- BN apply + ReLU + incremental final linear ----------------
__global__ __launch_bounds__(256) void k_bn(
    const float* __restrict__ z, float* __restrict__ h_out,
    const float* __restrict__ gamma, const float* __restrict__ beta,
    const float* __restrict__ linW, const float* __restrict__ lin_b,
    int layer, int write_h)
{
    __shared__ float sc[32], bi[32];
    __shared__ __align__(16) float hsm[8][32];
    int tid = threadIdx.x;
    int lane = tid & 31, wid = tid >> 5;
    if (tid < 32) {
        float s = g_stats[layer * 64 + tid];
        float q = g_stats[layer * 64 + 32 + tid];
        float mu  = s * (1.0f / NN);
        float var = q * (1.0f / NN) - mu * mu;
        float inv = rsqrtf(var + 1e-5f);
        float g = gamma[layer * 32 + tid] * inv;
        sc[tid] = g;
        bi[tid] = beta[layer * 32 + tid] - mu * g;
    }
    int myd = lane & 7;
    ull lwp[16];
#pragma unroll
    for (int c = 0; c < 32; c += 2) {
        float a = __ldg(&linW[layer * 256 + c * 8 + myd]);
        float b = __ldg(&linW[layer * 256 + (c + 1) * 8 + myd]);
        PACKX2(lwp[c / 2], a, b);
    }
    float lbv = __ldg(&lin_b[myd]);
    __syncthreads();

    int w  = blockIdx.x * (blockDim.x >> 5) + wid;
    int nw = gridDim.x * (blockDim.x >> 5);
    for (int i = w; i < NN; i += nw) {
        float zv = z[i * 32 + lane];
        float h = fmaxf(fmaf(zv, sc[lane], bi[lane]), 0.f);
        if (write_h) h_out[i * 32 + lane] = h;
        hsm[wid][lane] = h;
        __syncwarp();
        ull op0 = 0ull, op1 = 0ull;
        const ulonglong2* hrow = (const ulonglong2*)&hsm[wid][0];
#pragma unroll
        for (int q = 0; q < 8; q++) {
            ulonglong2 hq = hrow[q];
            FMAX2(op0, hq.x, lwp[2 * q + 0], op0);
            FMAX2(op1, hq.y, lwp[2 * q + 1], op1);
        }
        __syncwarp();
        ADDX2(op0, op0, op1);
        float ol, oh; UNPACKX2(ol, oh, op0);
        float v = ol + oh;
        if (lane < 8) {
            if (layer == 0) v += lbv;
            else            v += g_acc[i * 8 + lane];
            g_acc[i * 8 + lane] = v;
        }
    }
}

// ---------------- masked write-back (masks are int32), float4 per node -----
__global__ void k_mask(const float* __restrict__ x,
                       const int* __restrict__ nm,
                       const int* __restrict__ em,
                       float* __restrict__ out)
{
    int i = blockIdx.x * blockDim.x + threadIdx.x;
    if (i < NN) {
        const float4* x4 = (const float4*)x;
        const float4* a4 = (const float4*)g_acc;
        float4* o4 = (float4*)out;
        float4 xlo = __ldg(&x4[i * 2 + 0]);
        float4 xhi = __ldg(&x4[i * 2 + 1]);
        float4 alo = a4[i * 2 + 0];
        float4 ahi = a4[i * 2 + 1];
        bool n = (nm[i] != 0), e = (em[i] != 0);
        bool w14 = n || e;
        bool w5  = n;
        float4 olo = xlo, ohi = xhi;
        if (w14) { olo.y = alo.y; olo.z = alo.z; olo.w = alo.w; ohi.x = ahi.x; }
        if (w5)  { ohi.y = ahi.y; }
        o4[i * 2 + 0] = olo;
        o4[i * 2 + 1] = ohi;
    }
}

// ---------------- launch ----------------
extern "C" void kernel_launch(void* const* d_in, const int* in_sizes, int n_in,
                              void* d_out, int out_size)
{
    const float* x        = (const float*)d_in[0];
    const float* t        = (const float*)d_in[1];
    const int*   ei       = (const int*)d_in[2];
    const int*   node_mask = (const int*)d_in[3];
    const int*   edge_mask = (const int*)d_in[4];
    const float* W1_first = (const float*)d_in[7];
    const float* b1_first = (const float*)d_in[8];
    const float* W2_first = (const float*)d_in[9];
    const float* b2_first = (const float*)d_in[10];
    const float* W1_rest  = (const float*)d_in[11];
    const float* b1_rest  = (const float*)d_in[12];
    const float* W2_rest  = (const float*)d_in[13];
    const float* b2_rest  = (const float*)d_in[14];
    const float* eps      = (const float*)d_in[15];
    const float* bn_gamma = (const float*)d_in[16];
    const float* bn_beta  = (const float*)d_in[17];
    const float* lin_W    = (const float*)d_in[18];
    const float* lin_b    = (const float*)d_in[19];
    float* out = (float*)d_out;

    const int GB = 148 * 8;

    float* ag; cudaGetSymbolAddress((void**)&ag, g_agg);
    float* zz; cudaGetSymbolAddress((void**)&zz, g_z);
    float* hA; cudaGetSymbolAddress((void**)&hA, g_hA);
    float* hB; cudaGetSymbolAddress((void**)&hB, g_hB);

    k_hist<<<(EE + 255) / 256, 256>>>(ei);            // #0
    k_scan<<<256, 1024>>>();                          // #1
    k_fill<<<(EE + 255) / 256, 256>>>(ei);            // #2
    k_agg0<<<GB, 256>>>(x, ag, eps, t);               // #3  <- ncu captures this
    k_mlp<16><<<GB, 256>>>(ag, zz, W1_first, 9, b1_first, W2_first, b2_first, 0);
    k_bn<<<GB, 256>>>(zz, hA, bn_gamma, bn_beta, lin_W, lin_b, 0, 1);

    // Layer 1
    k_agg<<<GB, 256>>>(hA, ag, eps, 1);
    k_mlp<32><<<GB, 256>>>(ag, zz, W1_rest + 0 * 1024, 32, b1_rest + 0 * 32,
                           W2_rest + 0 * 1024, b2_rest + 0 * 32, 1);
    k_bn<<<GB, 256>>>(zz, hB, bn_gamma, bn_beta, lin_W, lin_b, 1, 1);

    // Layer 2
    k_agg<<<GB, 256>>>(hB, ag, eps, 2);
    k_mlp<32><<<GB, 256>>>(ag, zz, W1_rest + 1 * 1024, 32, b1_rest + 1 * 32,
                           W2_rest + 1 * 1024, b2_rest + 1 * 32, 2);
    k_bn<<<GB, 256>>>(zz, hA, bn_gamma, bn_beta, lin_W, lin_b, 2, 1);

    // Layer 3 (h never consumed afterward -> skip h store)
    k_agg<<<GB, 256>>>(hA, ag, eps, 3);
    k_mlp<32><<<GB, 256>>>(ag, zz, W1_rest + 2 * 1024, 32, b1_rest + 2 * 32,
                           W2_rest + 2 * 1024, b2_rest + 2 * 32, 3);
    k_bn<<<GB, 256>>>(zz, hB, bn_gamma, bn_beta, lin_W, lin_b, 3, 0);

    k_mask<<<(NN + 255) / 256, 256>>>(x, node_mask, edge_mask, out);
}